// round 4
// baseline (speedup 1.0000x reference)
#include <cuda_runtime.h>

// ---------------------------------------------------------------------------
// SpatioTemporalGNNLayer: out = relu(conv3x3(x,Ww)+Wb + conv3x3(agg,Bw)+Bb)
// agg[dst] = mean over incoming edges of x[src].
//
// CSR build (prep -> count -> scan+fill), then one fused per-node kernel:
// gather-mean + both convs via packed fma.rn.f32x2 with dual-alignment smem
// rows (no pack MOVs) and 2x output-channel blocking.
// ---------------------------------------------------------------------------

#define NNODES 4096
#define NEDGES 16384
#define NODE_ELEMS 4096          // 16*16*16
#define RS 34                    // row: [0,x0..x15,0 | x0..x15]  (136B)
#define CHS (18*RS)              // 18 rows (zero row above+below) = 612 floats
#define IMG_FLOATS (2*16*CHS)    // 19584 (x image + agg image)
#define NMASK (NNODES-1)

__device__ int g_deg[NNODES];
__device__ int g_cur[NNODES];
__device__ int g_off[NNODES + 1];
__device__ int g_srcs[NEDGES];
__device__ int g_is64;

// ---------------------------------------------------------------------------
// prologue 1: zero counters + detect edge dtype (int64 -> high words all 0)
__global__ void prep_kernel(const int* __restrict__ ei32, int E) {
    int i = blockIdx.x * blockDim.x + threadIdx.x;
    if (i < NNODES) { g_deg[i] = 0; g_cur[i] = 0; }
    if (blockIdx.x == 0 && threadIdx.x < 32) {
        int n = (E < 32) ? E : 32;
        int odd = (threadIdx.x < n) ? ei32[2 * threadIdx.x + 1] : 0;
        unsigned nz = __ballot_sync(0xffffffffu, odd != 0);
        if (threadIdx.x == 0) g_is64 = (nz == 0);
    }
}

__device__ __forceinline__ int load_idx(const int* ei32, int pos) {
    return g_is64 ? (ei32[2 * pos] & NMASK) : (ei32[pos] & NMASK);
}

// prologue 2: count in-degree
__global__ void count_kernel(const int* __restrict__ ei32, int E) {
    int e = blockIdx.x * blockDim.x + threadIdx.x;
    if (e < E) atomicAdd(&g_deg[load_idx(ei32, E + e)], 1);
}

// prologue 3: exclusive scan (warp-shuffle) + CSR fill, one 1024-thread CTA
__global__ void scanfill_kernel(const int* __restrict__ ei32, int E) {
    __shared__ int wsum[32];
    int t = threadIdx.x;
    int lane = t & 31, wid = t >> 5;
    int4 v = ((const int4*)g_deg)[t];
    int sum = v.x + v.y + v.z + v.w;
    int s = sum;
#pragma unroll
    for (int d = 1; d < 32; d <<= 1) {
        int n = __shfl_up_sync(0xffffffffu, s, d);
        if (lane >= d) s += n;
    }
    if (lane == 31) wsum[wid] = s;
    __syncthreads();
    if (wid == 0) {
        int ws = wsum[lane];
#pragma unroll
        for (int d = 1; d < 32; d <<= 1) {
            int n = __shfl_up_sync(0xffffffffu, ws, d);
            if (lane >= d) ws += n;
        }
        wsum[lane] = ws;
    }
    __syncthreads();
    int excl = ((wid > 0) ? wsum[wid - 1] : 0) + s - sum;
    g_off[4 * t + 0] = excl;
    g_off[4 * t + 1] = excl + v.x;
    g_off[4 * t + 2] = excl + v.x + v.y;
    g_off[4 * t + 3] = excl + v.x + v.y + v.z;
    if (t == 1023) g_off[NNODES] = wsum[31];
    __syncthreads();
    for (int e = t; e < E; e += 1024) {
        int sc = load_idx(ei32, e);
        int d  = load_idx(ei32, E + e);
        int pos = g_off[d] + atomicAdd(&g_cur[d], 1);
        g_srcs[pos] = sc;
    }
}

// ---------------------------------------------------------------------------
// packed fp32x2 fma; movs live INSIDE one asm block adjacent to the fma so
// ptxas can coalesce them into register-pair allocation.
__device__ __forceinline__ float2 ffma2(float2 a, float2 b, float2 c) {
    float2 d;
    asm("{\n\t"
        ".reg .b64 ta, tb, tc;\n\t"
        "mov.b64 ta, {%2, %3};\n\t"
        "mov.b64 tb, {%4, %5};\n\t"
        "mov.b64 tc, {%6, %7};\n\t"
        "fma.rn.f32x2 tc, ta, tb, tc;\n\t"
        "mov.b64 {%0, %1}, tc;\n\t"
        "}"
        : "=f"(d.x), "=f"(d.y)
        : "f"(a.x), "f"(a.y), "f"(b.x), "f"(b.y), "f"(c.x), "f"(c.y));
    return d;
}

// One input channel's 3x3 contribution to 16 px of one output row,
// for TWO output channels (co0, co1). Row layout (34 floats):
//   floats [0..17]  = [0, x0..x15, 0]   -> P pairs (taps -1,+1), ull 0..8
//   floats [18..33] = [x0..x15]         -> S pairs (tap 0),      ull 0..7
__device__ __forceinline__ void conv_ci(const float* __restrict__ img, int row,
                                        const float* __restrict__ w0,
                                        const float* __restrict__ w1,
                                        float2* acc0, float2* acc1) {
#pragma unroll
    for (int r = 0; r < 3; r++) {
        const float* rp = img + (row + r) * RS;
        const float2* Pp = (const float2*)rp;
        const float2* Sp = (const float2*)(rp + 18);
        float2 P[9], S[8];
#pragma unroll
        for (int k = 0; k < 9; k++) P[k] = Pp[k];
#pragma unroll
        for (int k = 0; k < 8; k++) S[k] = Sp[k];
        float wa0 = w0[3 * r], wb0 = w0[3 * r + 1], wc0 = w0[3 * r + 2];
        float wa1 = w1[3 * r], wb1 = w1[3 * r + 1], wc1 = w1[3 * r + 2];
        float2 a0 = make_float2(wa0, wa0), b0 = make_float2(wb0, wb0), c0 = make_float2(wc0, wc0);
        float2 a1 = make_float2(wa1, wa1), b1 = make_float2(wb1, wb1), c1 = make_float2(wc1, wc1);
#pragma unroll
        for (int k = 0; k < 8; k++) {
            acc0[k] = ffma2(a0, P[k],     acc0[k]);
            acc0[k] = ffma2(b0, S[k],     acc0[k]);
            acc0[k] = ffma2(c0, P[k + 1], acc0[k]);
            acc1[k] = ffma2(a1, P[k],     acc1[k]);
            acc1[k] = ffma2(b1, S[k],     acc1[k]);
            acc1[k] = ffma2(c1, P[k + 1], acc1[k]);
        }
    }
}

__global__ __launch_bounds__(128, 2) void gnn_main_kernel(
    const float* __restrict__ x,
    const float* __restrict__ Ww, const float* __restrict__ Wbias,
    const float* __restrict__ Bw, const float* __restrict__ Bbias,
    float* __restrict__ out) {
    extern __shared__ float sm[];
    float* sImg = sm;                 // 19584 floats (x then agg, 16 ch each)
    float* sW   = sm + IMG_FLOATS;    // 4608 floats (Ww 2304, Bw 2304)

    int tid  = threadIdx.x;
    int node = blockIdx.x;

    // zero image buffers (pads stay 0, data overwritten)
    float4* z4 = (float4*)sImg;
    for (int i = tid; i < IMG_FLOATS / 4; i += 128)
        z4[i] = make_float4(0.f, 0.f, 0.f, 0.f);
    // stage weights
    for (int i = tid; i < 4608; i += 128)
        sW[i] = (i < 2304) ? Ww[i] : Bw[i - 2304];

    // gather-mean over incoming edges: 8 float4 per thread
    const float4* xp = (const float4*)(x + (size_t)node * NODE_ELEMS);
    float4 a[8];
#pragma unroll
    for (int k = 0; k < 8; k++) a[k] = make_float4(0.f, 0.f, 0.f, 0.f);
    int beg = g_off[node], end = g_off[node + 1];
    for (int e = beg; e < end; e++) {
        int sc = g_srcs[e] & NMASK;
        const float4* sp = (const float4*)(x + (size_t)sc * NODE_ELEMS);
#pragma unroll
        for (int k = 0; k < 8; k++) {
            float4 v = __ldg(&sp[tid + 128 * k]);
            a[k].x += v.x; a[k].y += v.y; a[k].z += v.z; a[k].w += v.w;
        }
    }
    float inv = 1.0f / (float)max(end - beg, 1);

    __syncthreads();   // zeros in place before data stores

    // scatter x + agg into dual-alignment rows
#pragma unroll
    for (int k = 0; k < 8; k++) {
        int i4  = tid + 128 * k;          // float4 index within node
        int ci  = i4 >> 6;
        int rem = i4 & 63;
        int y   = rem >> 2;
        int m   = (rem & 3) * 4;          // pixel x-offset
        float* bx = sImg + ci * CHS + (y + 1) * RS;
        float* ba = sImg + (16 + ci) * CHS + (y + 1) * RS;
        float4 xv = xp[i4];
        bx[1 + m]  = xv.x; bx[2 + m]  = xv.y; bx[3 + m]  = xv.z; bx[4 + m]  = xv.w;
        bx[18 + m] = xv.x; bx[19 + m] = xv.y; bx[20 + m] = xv.z; bx[21 + m] = xv.w;
        float ax = a[k].x * inv, ay = a[k].y * inv, az = a[k].z * inv, aw = a[k].w * inv;
        ba[1 + m]  = ax; ba[2 + m]  = ay; ba[3 + m]  = az; ba[4 + m]  = aw;
        ba[18 + m] = ax; ba[19 + m] = ay; ba[20 + m] = az; ba[21 + m] = aw;
    }
    __syncthreads();

    // conv: thread (cog,row) computes 16 px for co0=2*cog, co1=2*cog+1
    int row = tid & 15;
    int cog = tid >> 4;
    int co0 = 2 * cog, co1 = co0 + 1;
    float bz0 = __ldg(&Wbias[co0]) + __ldg(&Bbias[co0]);
    float bz1 = __ldg(&Wbias[co1]) + __ldg(&Bbias[co1]);
    float2 acc0[8], acc1[8];
#pragma unroll
    for (int k = 0; k < 8; k++) {
        acc0[k] = make_float2(bz0, bz0);
        acc1[k] = make_float2(bz1, bz1);
    }

#pragma unroll 1
    for (int ci = 0; ci < 16; ci++) {
        conv_ci(sImg + ci * CHS, row,
                sW + (co0 * 16 + ci) * 9, sW + (co1 * 16 + ci) * 9, acc0, acc1);
        conv_ci(sImg + (16 + ci) * CHS, row,
                sW + 2304 + (co0 * 16 + ci) * 9, sW + 2304 + (co1 * 16 + ci) * 9,
                acc0, acc1);
    }

    float* o0 = out + (size_t)node * NODE_ELEMS + co0 * 256 + row * 16;
    float* o1 = out + (size_t)node * NODE_ELEMS + co1 * 256 + row * 16;
#pragma unroll
    for (int q = 0; q < 4; q++) {
        ((float4*)o0)[q] = make_float4(
            fmaxf(acc0[2 * q].x, 0.f), fmaxf(acc0[2 * q].y, 0.f),
            fmaxf(acc0[2 * q + 1].x, 0.f), fmaxf(acc0[2 * q + 1].y, 0.f));
        ((float4*)o1)[q] = make_float4(
            fmaxf(acc1[2 * q].x, 0.f), fmaxf(acc1[2 * q].y, 0.f),
            fmaxf(acc1[2 * q + 1].x, 0.f), fmaxf(acc1[2 * q + 1].y, 0.f));
    }
}

// ---------------------------------------------------------------------------
extern "C" void kernel_launch(void* const* d_in, const int* in_sizes, int n_in,
                              void* d_out, int out_size) {
    const float* x   = (const float*)d_in[0];
    const int*   ei  = (const int*)d_in[1];   // int32 view; prep detects dtype
    const float* Ww  = (const float*)d_in[2];
    const float* Wb  = (const float*)d_in[3];
    const float* Bw  = (const float*)d_in[4];
    const float* Bb  = (const float*)d_in[5];
    float*       out = (float*)d_out;

    int E = in_sizes[1] / 2;
    int N = in_sizes[0] / NODE_ELEMS;

    prep_kernel<<<(NNODES + 255) / 256, 256>>>(ei, E);
    count_kernel<<<(E + 255) / 256, 256>>>(ei, E);
    scanfill_kernel<<<1, 1024>>>(ei, E);

    int smem_bytes = (IMG_FLOATS + 4608) * (int)sizeof(float);  // 96768 B
    cudaFuncSetAttribute(gnn_main_kernel,
                         cudaFuncAttributeMaxDynamicSharedMemorySize, smem_bytes);
    gnn_main_kernel<<<N, 128, smem_bytes>>>(x, Ww, Wb, Bw, Bb, out);
}